// round 16
// baseline (speedup 1.0000x reference)
#include <cuda_runtime.h>
#include <cuda_bf16.h>
#include <mma.h>
#include <math.h>
#include <stdint.h>

using namespace nvcuda;

// ---------------------------------------------------------------------------
// WindowAttention (Swin): B_=2048 windows, N=49 tokens, C=256, H=8, Dh=32
// R16 = R10 resubmit (broker timeout x6 on this set): tf32 conversions
//       hoisted out of GEMM hot loops, GEMM staging via cp.async 2-stage.
// ---------------------------------------------------------------------------

#define B_WIN   2048
#define NTOK    49
#define DIM     256
#define NHEAD   8
#define DHEAD   32
#define NWIN    64
#define MROWS   (B_WIN * NTOK)        // 100352
#define QKV_N   (3 * DIM)             // 768
#define NN      (NTOK * NTOK)         // 2401

__device__ float g_qkv[(size_t)MROWS * QKV_N];    // ~308 MB
__device__ float g_attnout[(size_t)MROWS * DIM];  // ~103 MB (tf32 values)
__device__ float g_x[(size_t)MROWS * DIM];        // ~103 MB (tf32 copy of x)
__device__ float g_wq[QKV_N * DIM];               // tf32 qkv_w
__device__ float g_wp[DIM * DIM];                 // tf32 proj_w
__device__ float g_rpb[NHEAD * NN];               // gathered bias

__device__ __forceinline__ float f2tf32(float x) {
    unsigned u;
    asm("cvt.rna.tf32.f32 %0, %1;" : "=r"(u) : "f"(x));
    return __uint_as_float(u);
}

__device__ __forceinline__ void cp_async16(uint32_t saddr, const void* gptr) {
    asm volatile("cp.async.cg.shared.global [%0], [%1], 16;"
                 :: "r"(saddr), "l"(gptr));
}
#define CP_COMMIT() asm volatile("cp.async.commit_group;")
#define CP_WAIT0()  asm volatile("cp.async.wait_group 0;" ::: "memory")

__device__ __forceinline__ uint32_t smem_u32(const void* p) {
    return (uint32_t)__cvta_generic_to_shared(p);
}

// ---------------------------------------------------------------------------
// Generic fp32 -> tf32(RNA) conversion, float4 granularity. n4 = count/4.
// ---------------------------------------------------------------------------
__global__ void convert_tf32(const float* __restrict__ src,
                             float* __restrict__ dst, int n4)
{
    int i = blockIdx.x * blockDim.x + threadIdx.x;
    if (i >= n4) return;
    float4 v = reinterpret_cast<const float4*>(src)[i];
    v.x = f2tf32(v.x); v.y = f2tf32(v.y); v.z = f2tf32(v.z); v.w = f2tf32(v.w);
    reinterpret_cast<float4*>(dst)[i] = v;
}

// ---------------------------------------------------------------------------
// rpb precompute: g_rpb[h][ij] = rpb_table[rel_index[ij]*H + h]
// ---------------------------------------------------------------------------
__global__ void gather_rpb(const float* __restrict__ rpb_table,
                           const int* __restrict__ rel_index,
                           float* __restrict__ rpb_g)
{
    int idx = blockIdx.x * blockDim.x + threadIdx.x;
    if (idx >= NHEAD * NN) return;
    int h = idx / NN, ij = idx - h * NN;
    rpb_g[idx] = rpb_table[rel_index[ij] * NHEAD + h];
}

// ---------------------------------------------------------------------------
// tf32 GEMM: C[M,N] = A[M,K] @ B[N,K]^T + bias[N]
// A, B already tf32-converted. cp.async 2-stage staging, BKP=20 pad,
// 256 threads (8 warps: 4M x 2N), warp tile 32x64 (2x4 m16n16k8).
// Requires M%128==0, N%128==0, K%16==0.
// ---------------------------------------------------------------------------
#define BM 128
#define BN 128
#define BK 16
#define BKP 20   // padded row: 80B -> row starts rotate through 8 bank groups

__global__ __launch_bounds__(256, 2) void gemm_tf32_cp(
    const float* __restrict__ A, const float* __restrict__ Bm,
    const float* __restrict__ bias, float* __restrict__ C,
    int M, int N, int K)
{
    __shared__ __align__(16) float As[2][BM][BKP];
    __shared__ __align__(16) float Bs[2][BN][BKP];
    __shared__ float biasTile[16][BN];

    const int tid = threadIdx.x;
    const int wid = tid >> 5;
    const int wm  = wid & 3;          // warp row (4 x 32 rows)
    const int wn  = wid >> 2;         // warp col (2 x 64 cols)
    const int m0 = blockIdx.y * BM;
    const int n0 = blockIdx.x * BN;

    // Staging coords: 2 x 16B per matrix per thread.
    const int r0 = tid >> 2;          // 0..63
    const int r1 = r0 + 64;           // 64..127
    const int c4 = (tid & 3) * 4;     // 0,4,8,12

    const float* Ap0 = A + (size_t)(m0 + r0) * K + c4;
    const float* Ap1 = A + (size_t)(m0 + r1) * K + c4;
    const float* Bp0 = Bm + (size_t)(n0 + r0) * K + c4;
    const float* Bp1 = Bm + (size_t)(n0 + r1) * K + c4;

    // Per-buffer smem destinations (16B aligned: row stride 80B, c4*4B in {0,16,32,48})
    uint32_t dA0[2], dA1[2], dB0[2], dB1[2];
#pragma unroll
    for (int s = 0; s < 2; s++) {
        dA0[s] = smem_u32(&As[s][r0][c4]);
        dA1[s] = smem_u32(&As[s][r1][c4]);
        dB0[s] = smem_u32(&Bs[s][r0][c4]);
        dB1[s] = smem_u32(&Bs[s][r1][c4]);
    }

    for (int i = tid; i < 16 * BN; i += 256)
        biasTile[i >> 7][i & 127] = bias[n0 + (i & 127)];

    // Preload tile 0 into buffer 0
    cp_async16(dA0[0], Ap0);
    cp_async16(dA1[0], Ap1);
    cp_async16(dB0[0], Bp0);
    cp_async16(dB1[0], Bp1);
    CP_COMMIT();
    CP_WAIT0();
    __syncthreads();

    wmma::fragment<wmma::accumulator, 16, 16, 8, float> acc[2][4];
#pragma unroll
    for (int mi = 0; mi < 2; mi++)
#pragma unroll
        for (int ni = 0; ni < 4; ni++)
            wmma::load_matrix_sync(acc[mi][ni], &biasTile[0][wn * 64 + ni * 16],
                                   BN, wmma::mem_row_major);

    int buf = 0;
    for (int k0 = 0; k0 < K; k0 += BK) {
        const bool has_next = (k0 + BK) < K;
        if (has_next) {
            const int nb = buf ^ 1;
            cp_async16(dA0[nb], Ap0 + k0 + BK);
            cp_async16(dA1[nb], Ap1 + k0 + BK);
            cp_async16(dB0[nb], Bp0 + k0 + BK);
            cp_async16(dB1[nb], Bp1 + k0 + BK);
            CP_COMMIT();
        }

#pragma unroll
        for (int ks = 0; ks < BK; ks += 8) {
            wmma::fragment<wmma::matrix_a, 16, 16, 8, wmma::precision::tf32,
                           wmma::row_major> fa[2];
            wmma::fragment<wmma::matrix_b, 16, 16, 8, wmma::precision::tf32,
                           wmma::col_major> fb[4];
#pragma unroll
            for (int mi = 0; mi < 2; mi++)
                wmma::load_matrix_sync(fa[mi], &As[buf][wm * 32 + mi * 16][ks], BKP);
#pragma unroll
            for (int ni = 0; ni < 4; ni++)
                wmma::load_matrix_sync(fb[ni], &Bs[buf][wn * 64 + ni * 16][ks], BKP);
#pragma unroll
            for (int mi = 0; mi < 2; mi++)
#pragma unroll
                for (int ni = 0; ni < 4; ni++)
                    wmma::mma_sync(acc[mi][ni], fa[mi], fb[ni], acc[mi][ni]);
        }

        if (has_next) {
            CP_WAIT0();
            __syncthreads();
            buf ^= 1;
        }
    }

#pragma unroll
    for (int mi = 0; mi < 2; mi++)
#pragma unroll
        for (int ni = 0; ni < 4; ni++)
            wmma::store_matrix_sync(
                &C[(size_t)(m0 + wm * 32 + mi * 16) * N + n0 + wn * 64 + ni * 16],
                acc[mi][ni], N, wmma::mem_row_major);
}

// ---------------------------------------------------------------------------
// Windowed attention: one block per (window b, head h). 256 threads.
// Output written tf32-converted (feeds proj GEMM directly).
// ---------------------------------------------------------------------------
#define QPAD 36

__global__ __launch_bounds__(256) void win_attn(
    const float* __restrict__ qkv, const float* __restrict__ mask,
    const float* __restrict__ rpb_g, float* __restrict__ out)
{
    const int b = blockIdx.x;
    const int h = blockIdx.y;
    const int tid = threadIdx.x;
    const int wid = tid >> 5;
    const int lane = tid & 31;

    __shared__ float qs[50][QPAD];   // row 49 = scratch (i-pair overrun)
    __shared__ float ks[49][QPAD];
    __shared__ float vs[49][QPAD];
    __shared__ float lg[50][52];     // row 49 = scratch

    const float scale = 0.1767766952966369f;  // 32^-0.5

    const size_t base = (size_t)b * NTOK * QKV_N + (size_t)h * DHEAD;
    for (int idx = tid; idx < NTOK * (DHEAD / 4); idx += 256) {
        int t = idx >> 3, d4 = (idx & 7) * 4;
        size_t off = base + (size_t)t * QKV_N + d4;
        float4 q = *reinterpret_cast<const float4*>(&qkv[off]);
        float4 k = *reinterpret_cast<const float4*>(&qkv[off + DIM]);
        float4 v = *reinterpret_cast<const float4*>(&qkv[off + 2 * DIM]);
        q.x *= scale; q.y *= scale; q.z *= scale; q.w *= scale;
        *reinterpret_cast<float4*>(&qs[t][d4]) = q;
        *reinterpret_cast<float4*>(&ks[t][d4]) = k;
        *reinterpret_cast<float4*>(&vs[t][d4]) = v;
    }
    __syncthreads();

    const float* mk = mask + (size_t)(b & (NWIN - 1)) * NN;
    const float* bh = rpb_g + (size_t)h * NN;
    for (int idx = tid; idx < 25 * NTOK; idx += 256) {
        int i0 = idx / NTOK, j = idx - i0 * NTOK;
        int i1 = i0 + 25;
        const float4* q40 = reinterpret_cast<const float4*>(qs[i0]);
        const float4* q41 = reinterpret_cast<const float4*>(qs[i1]);
        const float4* k4  = reinterpret_cast<const float4*>(ks[j]);
        float s0 = 0.f, s1 = 0.f;
#pragma unroll
        for (int dd = 0; dd < 8; dd++) {
            float4 kv = k4[dd];
            float4 q0 = q40[dd];
            float4 q1 = q41[dd];
            s0 = fmaf(q0.x, kv.x, s0); s0 = fmaf(q0.y, kv.y, s0);
            s0 = fmaf(q0.z, kv.z, s0); s0 = fmaf(q0.w, kv.w, s0);
            s1 = fmaf(q1.x, kv.x, s1); s1 = fmaf(q1.y, kv.y, s1);
            s1 = fmaf(q1.z, kv.z, s1); s1 = fmaf(q1.w, kv.w, s1);
        }
        int e0i = i0 * NTOK + j;
        int e1i = i1 * NTOK + j;
        lg[i0][j] = s0 + bh[e0i] + mk[e0i];
        if (i1 < NTOK)
            lg[i1][j] = s1 + bh[e1i] + mk[e1i];
    }
    __syncthreads();

    // Softmax: warp per row; lane covers j=lane and j=lane+32.
    for (int r = wid; r < NTOK; r += 8) {
        int j1 = lane + 32;
        float v0 = (lane < NTOK) ? lg[r][lane] : -1e30f;
        float v1 = (j1 < NTOK) ? lg[r][j1] : -1e30f;
        float mx = fmaxf(v0, v1);
#pragma unroll
        for (int o = 16; o > 0; o >>= 1)
            mx = fmaxf(mx, __shfl_xor_sync(0xffffffffu, mx, o));
        float e0 = (lane < NTOK) ? __expf(v0 - mx) : 0.f;
        float e1 = (j1 < NTOK) ? __expf(v1 - mx) : 0.f;
        float sum = e0 + e1;
#pragma unroll
        for (int o = 16; o > 0; o >>= 1)
            sum += __shfl_xor_sync(0xffffffffu, sum, o);
        float inv = 1.f / sum;
        if (lane < NTOK) lg[r][lane] = e0 * inv;
        if (j1 < NTOK) lg[r][j1] = e1 * inv;
    }
    __syncthreads();

    // P @ V: thread handles (t0,d) and (t1=t0+25,d); emit tf32 values.
    float* outp = out + (size_t)b * NTOK * DIM + (size_t)h * DHEAD;
    for (int idx = tid; idx < 25 * DHEAD; idx += 256) {
        int t0 = idx >> 5, d = idx & 31;
        int t1 = t0 + 25;
        float s0 = 0.f, s1 = 0.f;
#pragma unroll
        for (int j = 0; j < NTOK; j++) {
            float vv = vs[j][d];
            s0 = fmaf(lg[t0][j], vv, s0);
            s1 = fmaf(lg[t1][j], vv, s1);
        }
        outp[(size_t)t0 * DIM + d] = f2tf32(s0);
        if (t1 < NTOK) outp[(size_t)t1 * DIM + d] = f2tf32(s1);
    }
}

// ---------------------------------------------------------------------------
// Launch
// Inputs: 0:x 1:mask 2:qkv_w 3:qkv_b 4:proj_w 5:proj_b 6:rpb_table 7:rel_index
// ---------------------------------------------------------------------------
extern "C" void kernel_launch(void* const* d_in, const int* in_sizes, int n_in,
                              void* d_out, int out_size)
{
    const float* x         = (const float*)d_in[0];
    const float* mask      = (const float*)d_in[1];
    const float* qkv_w     = (const float*)d_in[2];
    const float* qkv_b     = (const float*)d_in[3];
    const float* proj_w    = (const float*)d_in[4];
    const float* proj_b    = (const float*)d_in[5];
    const float* rpb_table = (const float*)d_in[6];
    const int*   rel_index = (const int*)d_in[7];
    float* out = (float*)d_out;

    float *qkv, *attn, *xc, *wq, *wp, *rpb_g;
    cudaGetSymbolAddress((void**)&qkv,   g_qkv);
    cudaGetSymbolAddress((void**)&attn,  g_attnout);
    cudaGetSymbolAddress((void**)&xc,    g_x);
    cudaGetSymbolAddress((void**)&wq,    g_wq);
    cudaGetSymbolAddress((void**)&wp,    g_wp);
    cudaGetSymbolAddress((void**)&rpb_g, g_rpb);

    // 0) Pre-convert operands to tf32 (RNA) + gather rpb
    {
        int n4w = QKV_N * DIM / 4;                 // 49152
        convert_tf32<<<(n4w + 255) / 256, 256>>>(qkv_w, wq, n4w);
        int n4p = DIM * DIM / 4;                   // 16384
        convert_tf32<<<(n4p + 255) / 256, 256>>>(proj_w, wp, n4p);
        int n4x = MROWS * DIM / 4;                 // 6422528
        convert_tf32<<<(n4x + 255) / 256, 256>>>(x, xc, n4x);
        gather_rpb<<<(NHEAD * NN + 255) / 256, 256>>>(rpb_table, rel_index, rpb_g);
    }

    // 1) QKV GEMM: (100352 x 256) @ (768 x 256)^T -> (100352 x 768)
    {
        dim3 grid(QKV_N / BN, MROWS / BM);   // (6, 784)
        gemm_tf32_cp<<<grid, 256>>>(xc, wq, qkv_b, qkv, MROWS, QKV_N, DIM);
    }

    // 2) Windowed attention (emits tf32 values)
    {
        dim3 grid(B_WIN, NHEAD);             // (2048, 8)
        win_attn<<<grid, 256>>>(qkv, mask, rpb_g, attn);
    }

    // 3) Proj GEMM: (100352 x 256) @ (256 x 256)^T -> (100352 x 256)
    {
        dim3 grid(DIM / BN, MROWS / BM);     // (2, 784)
        gemm_tf32_cp<<<grid, 256>>>(attn, wp, proj_b, out, MROWS, DIM, DIM);
    }
}